// round 9
// baseline (speedup 1.0000x reference)
#include <cuda_runtime.h>
#include <math.h>

#define B_   2
#define QL_  2048
#define KL_  4096
#define H_   1024
#define NH_  16
#define HD_  64
#define SCALE_ 0.125f
#define NEGINF (-INFINITY)

// ------------------------------------------------------------------
// Scratch (device globals: no allocations allowed)
// ------------------------------------------------------------------
__device__ float g_Q[(size_t)B_ * NH_ * QL_ * HD_];   // [b][h][q][hd]
__device__ float g_K[(size_t)B_ * NH_ * KL_ * HD_];   // [b][h][kv][hd]
__device__ float g_V[(size_t)B_ * NH_ * KL_ * HD_];
__device__ float g_ctx[(size_t)B_ * QL_ * H_];        // [b][q][h]
__device__ float g_pre[(size_t)B_ * QL_ * H_];        // pre-LN

// NOTE: parameter names deliberately avoid x/y/z/w — macro substitution is
// token-based, so a parameter named `w` would also rewrite `.w` member
// accesses (the round-6 compile failure).
#define FMA44(dst, va, vb) \
  dst[0][0] += va.x*vb.x; dst[0][1] += va.x*vb.y; dst[0][2] += va.x*vb.z; dst[0][3] += va.x*vb.w; \
  dst[1][0] += va.y*vb.x; dst[1][1] += va.y*vb.y; dst[1][2] += va.y*vb.z; dst[1][3] += va.y*vb.w; \
  dst[2][0] += va.z*vb.x; dst[2][1] += va.z*vb.y; dst[2][2] += va.z*vb.z; dst[2][3] += va.z*vb.w; \
  dst[3][0] += va.w*vb.x; dst[3][1] += va.w*vb.y; dst[3][2] += va.w*vb.z; dst[3][3] += va.w*vb.w;

// ------------------------------------------------------------------
// Tiled GEMM: C[M,N] = A[M,K] @ W[K,N] + bias (+ residual)
// mode 0: plain row-major out (+ optional residual)
// mode 1: out permuted to [b][nh][seq][hd] (Q/K/V projection)
//         skip_ptr (device): blocks whose rows are all < *skip_ptr (per-batch
//         position) are masked later and skipped entirely.
// ------------------------------------------------------------------
__global__ __launch_bounds__(256) void gemm_kernel(
    const float* __restrict__ A, const float* __restrict__ W,
    const float* __restrict__ bias, const float* __restrict__ residual,
    float* __restrict__ out, int M, int N, int K, int seq, int mode,
    const int* __restrict__ skip_ptr)
{
    __shared__ float As[16][68];   // [k][m]
    __shared__ float Ws[16][68];   // [k][n]

    const int m0 = blockIdx.y * 64;
    const int n0 = blockIdx.x * 64;

    if (mode == 1 && skip_ptr != nullptr) {
        int ansst = *skip_ptr;
        int s = m0 % seq;                 // 64 | seq, so whole block is one batch
        if (s + 64 <= ansst) return;      // rows fully masked downstream
    }

    const int tid = threadIdx.x;
    const int tx = tid & 15, ty = tid >> 4;

    float acc[4][4] = {};

    const int a_r = tid >> 2, a_c = (tid & 3) * 4;     // A tile load: 64x16
    const int w_r = tid >> 4, w_c = (tid & 15) * 4;    // W tile load: 16x64

    const float* Aptr = A + (size_t)(m0 + a_r) * K + a_c;
    const float* Wptr = W + (size_t)w_r * N + n0 + w_c;

    for (int k0 = 0; k0 < K; k0 += 16) {
        float4 av = *(const float4*)Aptr;  Aptr += 16;
        As[a_c + 0][a_r] = av.x;
        As[a_c + 1][a_r] = av.y;
        As[a_c + 2][a_r] = av.z;
        As[a_c + 3][a_r] = av.w;
        *(float4*)&Ws[w_r][w_c] = *(const float4*)Wptr;
        Wptr += (size_t)16 * N;
        __syncthreads();
        #pragma unroll
        for (int kk = 0; kk < 16; kk++) {
            float4 av2 = *(const float4*)&As[kk][ty * 4];
            float4 wv2 = *(const float4*)&Ws[kk][tx * 4];
            FMA44(acc, av2, wv2);
        }
        __syncthreads();
    }

    if (mode == 0) {
        #pragma unroll
        for (int i = 0; i < 4; i++) {
            int m = m0 + ty * 4 + i;
            int n = n0 + tx * 4;
            float4 r;
            r.x = acc[i][0] + bias[n + 0];
            r.y = acc[i][1] + bias[n + 1];
            r.z = acc[i][2] + bias[n + 2];
            r.w = acc[i][3] + bias[n + 3];
            if (residual != nullptr) {
                float4 q = *(const float4*)(residual + (size_t)m * N + n);
                r.x += q.x; r.y += q.y; r.z += q.z; r.w += q.w;
            }
            *(float4*)(out + (size_t)m * N + n) = r;
        }
    } else {
        #pragma unroll
        for (int i = 0; i < 4; i++) {
            int m  = m0 + ty * 4 + i;
            int bb = m / seq;
            int ss = m % seq;
            #pragma unroll
            for (int j = 0; j < 4; j++) {
                int n  = n0 + tx * 4 + j;
                int nh = n >> 6;
                int hd = n & 63;
                out[((size_t)(bb * NH_ + nh) * seq + ss) * HD_ + hd] =
                    acc[i][j] + bias[n];
            }
        }
    }
}

// ------------------------------------------------------------------
// Flash attention: one block per (q-tile-64, head, batch), 256 threads.
// Dynamic SMEM layout (floats): Qs[64hd][68q] Ks[64hd][68kv] Vs[64kv][68hd] Ps[64kv][68q]
// ------------------------------------------------------------------
#define ATT_SMEM_FLOATS (4 * 64 * 68)
#define ATT_SMEM_BYTES  (ATT_SMEM_FLOATS * 4)

__global__ __launch_bounds__(256) void attn_kernel(
    const float* __restrict__ Qg_, const float* __restrict__ Kg_,
    const float* __restrict__ Vg_, const int* __restrict__ amask,
    const int* __restrict__ ansst_ptr, float* __restrict__ ctx)
{
    extern __shared__ float sm[];
    float* Qs = sm;                 // [hd][q]   stride 68
    float* Ks = sm + 64 * 68;       // [hd][kv]  stride 68
    float* Vs = sm + 2 * 64 * 68;   // [kv][hd]  stride 68
    float* Ps = sm + 3 * 64 * 68;   // [kv][q]   stride 68

    const int qt = blockIdx.x, h = blockIdx.y, b = blockIdx.z;
    const int tid = threadIdx.x;
    const int tx = tid & 15, ty = tid >> 4;
    const int ansst = *ansst_ptr;

    const float* Qg = Qg_ + ((size_t)(b * NH_ + h) * QL_ + qt * 64) * HD_;
    const float* Kg = Kg_ + (size_t)(b * NH_ + h) * KL_ * HD_;
    const float* Vg = Vg_ + (size_t)(b * NH_ + h) * KL_ * HD_;

    // Load Q tile transposed, fold in softmax scale
    {
        const int r = tid >> 2, cb = (tid & 3) * 4;
        #pragma unroll
        for (int rep = 0; rep < 4; rep++) {
            int d0 = cb + rep * 16;
            float4 v = *(const float4*)(Qg + (size_t)r * HD_ + d0);
            Qs[(d0 + 0) * 68 + r] = v.x * SCALE_;
            Qs[(d0 + 1) * 68 + r] = v.y * SCALE_;
            Qs[(d0 + 2) * 68 + r] = v.z * SCALE_;
            Qs[(d0 + 3) * 68 + r] = v.w * SCALE_;
        }
    }

    int qm[4];
    float m_i[4], l_i[4], o[4][4] = {};
    #pragma unroll
    for (int i = 0; i < 4; i++) {
        m_i[i] = NEGINF;
        l_i[i] = 0.0f;
        qm[i] = amask[b * QL_ + qt * 64 + ty * 4 + i];
    }

    const int t0 = (ansst > 0 ? ansst : 0) >> 6;   // first unmasked kv tile
    for (int t = t0; t < KL_ / 64; t++) {
        const int kv0 = t * 64;
        // load K (transposed) and V (natural) tiles
        {
            const int r = tid >> 2, cb = (tid & 3) * 4;
            #pragma unroll
            for (int rep = 0; rep < 4; rep++) {
                int d0 = cb + rep * 16;
                float4 kv = *(const float4*)(Kg + (size_t)(kv0 + r) * HD_ + d0);
                Ks[(d0 + 0) * 68 + r] = kv.x;
                Ks[(d0 + 1) * 68 + r] = kv.y;
                Ks[(d0 + 2) * 68 + r] = kv.z;
                Ks[(d0 + 3) * 68 + r] = kv.w;
                float4 vv = *(const float4*)(Vg + (size_t)(kv0 + r) * HD_ + d0);
                *(float4*)&Vs[r * 68 + d0] = vv;
            }
        }
        __syncthreads();

        // S = (Q*scale) @ K^T
        float s[4][4] = {};
        #pragma unroll 8
        for (int d = 0; d < HD_; d++) {
            float4 qv = *(const float4*)&Qs[d * 68 + ty * 4];
            float4 kv4 = *(const float4*)&Ks[d * 68 + tx * 4];
            FMA44(s, qv, kv4);
        }
        // masks: key positions < answer_start_idx, and query padding mask
        #pragma unroll
        for (int i = 0; i < 4; i++) {
            #pragma unroll
            for (int j = 0; j < 4; j++) {
                int kv = kv0 + tx * 4 + j;
                if (kv < ansst || qm[i] == 0) s[i][j] = NEGINF;
            }
        }
        // row max (over 4 local + across 16 tx lanes)
        float mt[4];
        #pragma unroll
        for (int i = 0; i < 4; i++)
            mt[i] = fmaxf(fmaxf(s[i][0], s[i][1]), fmaxf(s[i][2], s[i][3]));
        #pragma unroll
        for (int off = 8; off > 0; off >>= 1) {
            #pragma unroll
            for (int i = 0; i < 4; i++)
                mt[i] = fmaxf(mt[i], __shfl_xor_sync(0xffffffffu, mt[i], off));
        }
        float sc[4], lt[4];
        #pragma unroll
        for (int i = 0; i < 4; i++) {
            float mn = fmaxf(m_i[i], mt[i]);
            sc[i] = __expf(m_i[i] - mn);
            m_i[i] = mn;
            lt[i] = 0.0f;
            #pragma unroll
            for (int j = 0; j < 4; j++) {
                float p = __expf(s[i][j] - mn);
                Ps[(tx * 4 + j) * 68 + ty * 4 + i] = p;
                lt[i] += p;
            }
        }
        #pragma unroll
        for (int off = 8; off > 0; off >>= 1) {
            #pragma unroll
            for (int i = 0; i < 4; i++)
                lt[i] += __shfl_xor_sync(0xffffffffu, lt[i], off);
        }
        #pragma unroll
        for (int i = 0; i < 4; i++) {
            l_i[i] = l_i[i] * sc[i] + lt[i];
            o[i][0] *= sc[i]; o[i][1] *= sc[i]; o[i][2] *= sc[i]; o[i][3] *= sc[i];
        }
        __syncthreads();   // Ps visible to all

        // O += P @ V
        #pragma unroll 8
        for (int kv = 0; kv < 64; kv++) {
            float4 pv4 = *(const float4*)&Ps[kv * 68 + ty * 4];
            float4 vv4 = *(const float4*)&Vs[kv * 68 + tx * 4];
            FMA44(o, pv4, vv4);
        }
        __syncthreads();   // before next tile overwrites Ks/Vs/Ps
    }

    // write context in [b][q][h] layout
    #pragma unroll
    for (int i = 0; i < 4; i++) {
        int q = qt * 64 + ty * 4 + i;
        float inv = 1.0f / l_i[i];
        float4 r;
        r.x = o[i][0] * inv; r.y = o[i][1] * inv;
        r.z = o[i][2] * inv; r.w = o[i][3] * inv;
        *(float4*)(ctx + (size_t)(b * QL_ + q) * H_ + h * HD_ + tx * 4) = r;
    }
}

// ------------------------------------------------------------------
// LayerNorm: one block (256 threads) per row of 1024
// ------------------------------------------------------------------
__global__ __launch_bounds__(256) void ln_kernel(
    const float* __restrict__ x, const float* __restrict__ w,
    const float* __restrict__ bb, float* __restrict__ out)
{
    const int row = blockIdx.x, tid = threadIdx.x;
    const float* xr = x + (size_t)row * H_;
    float4 v = *(const float4*)(xr + tid * 4);
    float s = v.x + v.y + v.z + v.w;
    #pragma unroll
    for (int off = 16; off > 0; off >>= 1) s += __shfl_xor_sync(0xffffffffu, s, off);
    __shared__ float b1[8], b2[8];
    int wid = tid >> 5, lane = tid & 31;
    if (lane == 0) b1[wid] = s;
    __syncthreads();
    float tot = 0.0f;
    #pragma unroll
    for (int i = 0; i < 8; i++) tot += b1[i];
    float mean = tot * (1.0f / H_);
    float dx = v.x - mean, dy = v.y - mean, dz = v.z - mean, dw = v.w - mean;
    float s2 = dx * dx + dy * dy + dz * dz + dw * dw;
    #pragma unroll
    for (int off = 16; off > 0; off >>= 1) s2 += __shfl_xor_sync(0xffffffffu, s2, off);
    if (lane == 0) b2[wid] = s2;
    __syncthreads();
    float tot2 = 0.0f;
    #pragma unroll
    for (int i = 0; i < 8; i++) tot2 += b2[i];
    float rstd = rsqrtf(tot2 * (1.0f / H_) + 1e-5f);
    float4 wv = *(const float4*)(w + tid * 4);
    float4 bv = *(const float4*)(bb + tid * 4);
    float4 r;
    r.x = dx * rstd * wv.x + bv.x;
    r.y = dy * rstd * wv.y + bv.y;
    r.z = dz * rstd * wv.z + bv.z;
    r.w = dw * rstd * wv.w + bv.w;
    *(float4*)(out + (size_t)row * H_ + tid * 4) = r;
}

// ------------------------------------------------------------------
extern "C" void kernel_launch(void* const* d_in, const int* in_sizes, int n_in,
                              void* d_out, int out_size)
{
    const float* query = (const float*)d_in[0];
    const float* know  = (const float*)d_in[1];
    const int*   amask = (const int*)d_in[2];
    const int*   ansst = (const int*)d_in[3];   // low 32 bits valid for int32/int64
    const float* Wq = (const float*)d_in[4];
    const float* bq = (const float*)d_in[5];
    const float* Wk = (const float*)d_in[6];
    const float* bk = (const float*)d_in[7];
    const float* Wv = (const float*)d_in[8];
    const float* bv = (const float*)d_in[9];
    const float* Wo = (const float*)d_in[10];
    const float* bo = (const float*)d_in[11];
    const float* lnw = (const float*)d_in[12];
    const float* lnb = (const float*)d_in[13];
    float* out = (float*)d_out;

    float *Qb, *Kb, *Vb, *Cb, *Pb;
    cudaGetSymbolAddress((void**)&Qb, g_Q);
    cudaGetSymbolAddress((void**)&Kb, g_K);
    cudaGetSymbolAddress((void**)&Vb, g_V);
    cudaGetSymbolAddress((void**)&Cb, g_ctx);
    cudaGetSymbolAddress((void**)&Pb, g_pre);

    const dim3 blk(256);

    // Q / K / V projections (K/V blocks below answer_start_idx are skipped)
    gemm_kernel<<<dim3(H_ / 64, (B_ * QL_) / 64), blk>>>(
        query, Wq, bq, nullptr, Qb, B_ * QL_, H_, H_, QL_, 1, nullptr);
    gemm_kernel<<<dim3(H_ / 64, (B_ * KL_) / 64), blk>>>(
        know, Wk, bk, nullptr, Kb, B_ * KL_, H_, H_, KL_, 1, ansst);
    gemm_kernel<<<dim3(H_ / 64, (B_ * KL_) / 64), blk>>>(
        know, Wv, bv, nullptr, Vb, B_ * KL_, H_, H_, KL_, 1, ansst);

    // Flash attention
    cudaFuncSetAttribute(attn_kernel, cudaFuncAttributeMaxDynamicSharedMemorySize,
                         ATT_SMEM_BYTES);
    attn_kernel<<<dim3(QL_ / 64, NH_, B_), blk, ATT_SMEM_BYTES>>>(
        Qb, Kb, Vb, amask, ansst, Cb);

    // Output projection + bias + residual
    gemm_kernel<<<dim3(H_ / 64, (B_ * QL_) / 64), blk>>>(
        Cb, Wo, bo, query, Pb, B_ * QL_, H_, H_, 0, 0, nullptr);

    // LayerNorm
    ln_kernel<<<B_ * QL_, blk>>>(Pb, lnw, lnb, out);
}

// round 10
// speedup vs baseline: 1.3416x; 1.3416x over previous
#include <cuda_runtime.h>
#include <math.h>
#include <stdint.h>

#define B_   2
#define QL_  2048
#define KL_  4096
#define H_   1024
#define NH_  16
#define HD_  64
#define SCALE_ 0.125f
#define NEGINF (-INFINITY)

// ------------------------------------------------------------------
// Scratch (device globals: no allocations allowed)
// ------------------------------------------------------------------
__device__ float g_Q[(size_t)B_ * NH_ * QL_ * HD_];   // [b][h][q][hd]
__device__ float g_K[(size_t)B_ * NH_ * KL_ * HD_];   // [b][h][kv][hd]
__device__ float g_V[(size_t)B_ * NH_ * KL_ * HD_];
__device__ float g_ctx[(size_t)B_ * QL_ * H_];        // [b][q][h]
__device__ float g_pre[(size_t)B_ * QL_ * H_];        // pre-LN

// NOTE: parameter names deliberately avoid x/y/z/w (token-based macro
// substitution would rewrite `.w` member accesses — round-6 failure).
#define FMA44(dst, va, vb) \
  dst[0][0] += va.x*vb.x; dst[0][1] += va.x*vb.y; dst[0][2] += va.x*vb.z; dst[0][3] += va.x*vb.w; \
  dst[1][0] += va.y*vb.x; dst[1][1] += va.y*vb.y; dst[1][2] += va.y*vb.z; dst[1][3] += va.y*vb.w; \
  dst[2][0] += va.z*vb.x; dst[2][1] += va.z*vb.y; dst[2][2] += va.z*vb.z; dst[2][3] += va.z*vb.w; \
  dst[3][0] += va.w*vb.x; dst[3][1] += va.w*vb.y; dst[3][2] += va.w*vb.z; dst[3][3] += va.w*vb.w;

// ------------------------------------------------------------------
// tf32 helpers
// ------------------------------------------------------------------
__device__ __forceinline__ uint32_t f2tf(float f) {
    uint32_t r;
    asm("cvt.rna.tf32.f32 %0, %1;" : "=r"(r) : "f"(f));
    return r;
}

__device__ __forceinline__ void mma_tf32(float* d, const uint32_t* a, const uint32_t* b) {
    asm volatile(
        "mma.sync.aligned.m16n8k8.row.col.f32.tf32.tf32.f32 "
        "{%0,%1,%2,%3}, {%4,%5,%6,%7}, {%8,%9}, {%0,%1,%2,%3};"
        : "+f"(d[0]), "+f"(d[1]), "+f"(d[2]), "+f"(d[3])
        : "r"(a[0]), "r"(a[1]), "r"(a[2]), "r"(a[3]), "r"(b[0]), "r"(b[1]));
}

// ------------------------------------------------------------------
// tf32 tensor-core GEMM: C[M,N] = A[M,K] @ W[K,N] + bias (+ residual)
// CTA tile 128x128, 8 warps as 4(m) x 2(n), each warp 32x64 via
// 2x8 mma.m16n8k8 tiles, k-chunk 32 (4 mma k-steps of 8).
// mode 0: row-major out (+ optional residual)
// mode 1: out permuted to [b][nh][seq][hd]; skip fully-masked K/V blocks.
// Requires M%128==0, N%128==0, K%32==0 (holds for all four calls).
// ------------------------------------------------------------------
__global__ __launch_bounds__(256) void gemm_tf32_kernel(
    const float* __restrict__ A, const float* __restrict__ W,
    const float* __restrict__ bias, const float* __restrict__ residual,
    float* __restrict__ out, int M, int N, int K, int seq, int mode,
    const int* __restrict__ skip_ptr)
{
    // stride 136 floats: 136 mod 32 == 8 -> fragment-load bank = t*8+g,
    // all 32 lanes distinct (conflict-free) for every a/b fragment.
    __shared__ float As[32][136];   // [k][m]
    __shared__ float Ws[32][136];   // [k][n]

    const int m0 = blockIdx.y * 128;
    const int n0 = blockIdx.x * 128;

    if (mode == 1 && skip_ptr != nullptr) {
        int ansst = *skip_ptr;
        int s = m0 % seq;                  // 128 | seq: block within one batch
        if (s + 128 <= ansst) return;      // rows fully masked downstream
    }

    const int tid  = threadIdx.x;
    const int wid  = tid >> 5, lane = tid & 31;
    const int wm   = (wid >> 1) * 32;      // warp row offset in tile
    const int wn   = (wid & 1) * 64;       // warp col offset in tile
    const int g    = lane >> 2, t = lane & 3;

    float d[2][8][4];
    #pragma unroll
    for (int mm = 0; mm < 2; mm++)
        #pragma unroll
        for (int nn = 0; nn < 8; nn++)
            #pragma unroll
            for (int i = 0; i < 4; i++) d[mm][nn][i] = 0.0f;

    for (int k0 = 0; k0 < K; k0 += 32) {
        // Load A 128x32 (transpose to [k][m]) and W 32x128 (direct [k][n])
        #pragma unroll
        for (int i = 0; i < 4; i++) {
            int idx  = tid + i * 256;
            int arow = idx >> 3, ac = (idx & 7) * 4;         // A: 8 float4/row
            float4 av = *(const float4*)(A + (size_t)(m0 + arow) * K + k0 + ac);
            As[ac + 0][arow] = av.x;
            As[ac + 1][arow] = av.y;
            As[ac + 2][arow] = av.z;
            As[ac + 3][arow] = av.w;
            int wrow = idx >> 5, wc = (idx & 31) * 4;        // W: 32 float4/row
            *(float4*)&Ws[wrow][wc] =
                *(const float4*)(W + (size_t)(k0 + wrow) * N + n0 + wc);
        }
        __syncthreads();

        #pragma unroll
        for (int kc = 0; kc < 32; kc += 8) {
            uint32_t a[2][4], b[8][2];
            #pragma unroll
            for (int mm = 0; mm < 2; mm++) {
                int mr = wm + mm * 16 + g;
                a[mm][0] = f2tf(As[kc + t    ][mr]);
                a[mm][1] = f2tf(As[kc + t    ][mr + 8]);
                a[mm][2] = f2tf(As[kc + t + 4][mr]);
                a[mm][3] = f2tf(As[kc + t + 4][mr + 8]);
            }
            #pragma unroll
            for (int nn = 0; nn < 8; nn++) {
                int nc = wn + nn * 8 + g;
                b[nn][0] = f2tf(Ws[kc + t    ][nc]);
                b[nn][1] = f2tf(Ws[kc + t + 4][nc]);
            }
            #pragma unroll
            for (int mm = 0; mm < 2; mm++)
                #pragma unroll
                for (int nn = 0; nn < 8; nn++)
                    mma_tf32(d[mm][nn], a[mm], b[nn]);
        }
        __syncthreads();
    }

    // Epilogue. c-fragment layout: d0 -> (g, 2t), d1 -> (g, 2t+1),
    //                              d2 -> (g+8, 2t), d3 -> (g+8, 2t+1)
    #pragma unroll
    for (int mm = 0; mm < 2; mm++) {
        #pragma unroll
        for (int nn = 0; nn < 8; nn++) {
            int r0 = m0 + wm + mm * 16 + g;
            int r1 = r0 + 8;
            int c0 = n0 + wn + nn * 8 + t * 2;
            float v00 = d[mm][nn][0] + bias[c0];
            float v01 = d[mm][nn][1] + bias[c0 + 1];
            float v10 = d[mm][nn][2] + bias[c0];
            float v11 = d[mm][nn][3] + bias[c0 + 1];
            if (mode == 0) {
                if (residual != nullptr) {
                    v00 += residual[(size_t)r0 * N + c0];
                    v01 += residual[(size_t)r0 * N + c0 + 1];
                    v10 += residual[(size_t)r1 * N + c0];
                    v11 += residual[(size_t)r1 * N + c0 + 1];
                }
                out[(size_t)r0 * N + c0]     = v00;
                out[(size_t)r0 * N + c0 + 1] = v01;
                out[(size_t)r1 * N + c0]     = v10;
                out[(size_t)r1 * N + c0 + 1] = v11;
            } else {
                // permute to [b][nh][seq][hd]; c0 even so c0/c0+1 share nh
                int nh = c0 >> 6, hd = c0 & 63;
                int bb0 = r0 / seq, ss0 = r0 % seq;
                int bb1 = r1 / seq, ss1 = r1 % seq;
                size_t o0 = ((size_t)(bb0 * NH_ + nh) * seq + ss0) * HD_ + hd;
                size_t o1 = ((size_t)(bb1 * NH_ + nh) * seq + ss1) * HD_ + hd;
                out[o0]     = v00;
                out[o0 + 1] = v01;
                out[o1]     = v10;
                out[o1 + 1] = v11;
            }
        }
    }
}

// ------------------------------------------------------------------
// Flash attention (fp32, unchanged from passing R9 baseline):
// one block per (q-tile-64, head, batch), 256 threads.
// SMEM: Qs[64hd][68q] Ks[64hd][68kv] Vs[64kv][68hd] Ps[64kv][68q]
// ------------------------------------------------------------------
#define ATT_SMEM_FLOATS (4 * 64 * 68)
#define ATT_SMEM_BYTES  (ATT_SMEM_FLOATS * 4)

__global__ __launch_bounds__(256) void attn_kernel(
    const float* __restrict__ Qg_, const float* __restrict__ Kg_,
    const float* __restrict__ Vg_, const int* __restrict__ amask,
    const int* __restrict__ ansst_ptr, float* __restrict__ ctx)
{
    extern __shared__ float sm[];
    float* Qs = sm;                 // [hd][q]   stride 68
    float* Ks = sm + 64 * 68;       // [hd][kv]  stride 68
    float* Vs = sm + 2 * 64 * 68;   // [kv][hd]  stride 68
    float* Ps = sm + 3 * 64 * 68;   // [kv][q]   stride 68

    const int qt = blockIdx.x, h = blockIdx.y, b = blockIdx.z;
    const int tid = threadIdx.x;
    const int tx = tid & 15, ty = tid >> 4;
    const int ansst = *ansst_ptr;

    const float* Qg = Qg_ + ((size_t)(b * NH_ + h) * QL_ + qt * 64) * HD_;
    const float* Kg = Kg_ + (size_t)(b * NH_ + h) * KL_ * HD_;
    const float* Vg = Vg_ + (size_t)(b * NH_ + h) * KL_ * HD_;

    // Load Q tile transposed, fold in softmax scale
    {
        const int r = tid >> 2, cb = (tid & 3) * 4;
        #pragma unroll
        for (int rep = 0; rep < 4; rep++) {
            int d0 = cb + rep * 16;
            float4 v = *(const float4*)(Qg + (size_t)r * HD_ + d0);
            Qs[(d0 + 0) * 68 + r] = v.x * SCALE_;
            Qs[(d0 + 1) * 68 + r] = v.y * SCALE_;
            Qs[(d0 + 2) * 68 + r] = v.z * SCALE_;
            Qs[(d0 + 3) * 68 + r] = v.w * SCALE_;
        }
    }

    int qm[4];
    float m_i[4], l_i[4], o[4][4] = {};
    #pragma unroll
    for (int i = 0; i < 4; i++) {
        m_i[i] = NEGINF;
        l_i[i] = 0.0f;
        qm[i] = amask[b * QL_ + qt * 64 + ty * 4 + i];
    }

    const int t0 = (ansst > 0 ? ansst : 0) >> 6;   // first unmasked kv tile
    for (int t = t0; t < KL_ / 64; t++) {
        const int kv0 = t * 64;
        {
            const int r = tid >> 2, cb = (tid & 3) * 4;
            #pragma unroll
            for (int rep = 0; rep < 4; rep++) {
                int d0 = cb + rep * 16;
                float4 kv = *(const float4*)(Kg + (size_t)(kv0 + r) * HD_ + d0);
                Ks[(d0 + 0) * 68 + r] = kv.x;
                Ks[(d0 + 1) * 68 + r] = kv.y;
                Ks[(d0 + 2) * 68 + r] = kv.z;
                Ks[(d0 + 3) * 68 + r] = kv.w;
                float4 vv = *(const float4*)(Vg + (size_t)(kv0 + r) * HD_ + d0);
                *(float4*)&Vs[r * 68 + d0] = vv;
            }
        }
        __syncthreads();

        // S = (Q*scale) @ K^T
        float s[4][4] = {};
        #pragma unroll 8
        for (int d = 0; d < HD_; d++) {
            float4 qv  = *(const float4*)&Qs[d * 68 + ty * 4];
            float4 kv4 = *(const float4*)&Ks[d * 68 + tx * 4];
            FMA44(s, qv, kv4);
        }
        #pragma unroll
        for (int i = 0; i < 4; i++) {
            #pragma unroll
            for (int j = 0; j < 4; j++) {
                int kv = kv0 + tx * 4 + j;
                if (kv < ansst || qm[i] == 0) s[i][j] = NEGINF;
            }
        }
        float mt[4];
        #pragma unroll
        for (int i = 0; i < 4; i++)
            mt[i] = fmaxf(fmaxf(s[i][0], s[i][1]), fmaxf(s[i][2], s[i][3]));
        #pragma unroll
        for (int off = 8; off > 0; off >>= 1) {
            #pragma unroll
            for (int i = 0; i < 4; i++)
                mt[i] = fmaxf(mt[i], __shfl_xor_sync(0xffffffffu, mt[i], off));
        }
        float sc[4], lt[4];
        #pragma unroll
        for (int i = 0; i < 4; i++) {
            float mn = fmaxf(m_i[i], mt[i]);
            sc[i] = __expf(m_i[i] - mn);
            m_i[i] = mn;
            lt[i] = 0.0f;
            #pragma unroll
            for (int j = 0; j < 4; j++) {
                float p = __expf(s[i][j] - mn);
                Ps[(tx * 4 + j) * 68 + ty * 4 + i] = p;
                lt[i] += p;
            }
        }
        #pragma unroll
        for (int off = 8; off > 0; off >>= 1) {
            #pragma unroll
            for (int i = 0; i < 4; i++)
                lt[i] += __shfl_xor_sync(0xffffffffu, lt[i], off);
        }
        #pragma unroll
        for (int i = 0; i < 4; i++) {
            l_i[i] = l_i[i] * sc[i] + lt[i];
            o[i][0] *= sc[i]; o[i][1] *= sc[i]; o[i][2] *= sc[i]; o[i][3] *= sc[i];
        }
        __syncthreads();

        // O += P @ V
        #pragma unroll 8
        for (int kv = 0; kv < 64; kv++) {
            float4 pv4 = *(const float4*)&Ps[kv * 68 + ty * 4];
            float4 vv4 = *(const float4*)&Vs[kv * 68 + tx * 4];
            FMA44(o, pv4, vv4);
        }
        __syncthreads();
    }

    #pragma unroll
    for (int i = 0; i < 4; i++) {
        int q = qt * 64 + ty * 4 + i;
        float inv = 1.0f / l_i[i];
        float4 r;
        r.x = o[i][0] * inv; r.y = o[i][1] * inv;
        r.z = o[i][2] * inv; r.w = o[i][3] * inv;
        *(float4*)(ctx + (size_t)(b * QL_ + q) * H_ + h * HD_ + tx * 4) = r;
    }
}

// ------------------------------------------------------------------
// LayerNorm: one block (256 threads) per row of 1024
// ------------------------------------------------------------------
__global__ __launch_bounds__(256) void ln_kernel(
    const float* __restrict__ x, const float* __restrict__ w,
    const float* __restrict__ bb, float* __restrict__ out)
{
    const int row = blockIdx.x, tid = threadIdx.x;
    const float* xr = x + (size_t)row * H_;
    float4 v = *(const float4*)(xr + tid * 4);
    float s = v.x + v.y + v.z + v.w;
    #pragma unroll
    for (int off = 16; off > 0; off >>= 1) s += __shfl_xor_sync(0xffffffffu, s, off);
    __shared__ float b1[8], b2[8];
    int wid = tid >> 5, lane = tid & 31;
    if (lane == 0) b1[wid] = s;
    __syncthreads();
    float tot = 0.0f;
    #pragma unroll
    for (int i = 0; i < 8; i++) tot += b1[i];
    float mean = tot * (1.0f / H_);
    float dx = v.x - mean, dy = v.y - mean, dz = v.z - mean, dw = v.w - mean;
    float s2 = dx * dx + dy * dy + dz * dz + dw * dw;
    #pragma unroll
    for (int off = 16; off > 0; off >>= 1) s2 += __shfl_xor_sync(0xffffffffu, s2, off);
    if (lane == 0) b2[wid] = s2;
    __syncthreads();
    float tot2 = 0.0f;
    #pragma unroll
    for (int i = 0; i < 8; i++) tot2 += b2[i];
    float rstd = rsqrtf(tot2 * (1.0f / H_) + 1e-5f);
    float4 wv = *(const float4*)(w + tid * 4);
    float4 bv = *(const float4*)(bb + tid * 4);
    float4 r;
    r.x = dx * rstd * wv.x + bv.x;
    r.y = dy * rstd * wv.y + bv.y;
    r.z = dz * rstd * wv.z + bv.z;
    r.w = dw * rstd * wv.w + bv.w;
    *(float4*)(out + (size_t)row * H_ + tid * 4) = r;
}

// ------------------------------------------------------------------
extern "C" void kernel_launch(void* const* d_in, const int* in_sizes, int n_in,
                              void* d_out, int out_size)
{
    const float* query = (const float*)d_in[0];
    const float* know  = (const float*)d_in[1];
    const int*   amask = (const int*)d_in[2];
    const int*   ansst = (const int*)d_in[3];
    const float* Wq = (const float*)d_in[4];
    const float* bq = (const float*)d_in[5];
    const float* Wk = (const float*)d_in[6];
    const float* bk = (const float*)d_in[7];
    const float* Wv = (const float*)d_in[8];
    const float* bv = (const float*)d_in[9];
    const float* Wo = (const float*)d_in[10];
    const float* bo = (const float*)d_in[11];
    const float* lnw = (const float*)d_in[12];
    const float* lnb = (const float*)d_in[13];
    float* out = (float*)d_out;

    float *Qb, *Kb, *Vb, *Cb, *Pb;
    cudaGetSymbolAddress((void**)&Qb, g_Q);
    cudaGetSymbolAddress((void**)&Kb, g_K);
    cudaGetSymbolAddress((void**)&Vb, g_V);
    cudaGetSymbolAddress((void**)&Cb, g_ctx);
    cudaGetSymbolAddress((void**)&Pb, g_pre);

    const dim3 blk(256);

    // Q / K / V projections — tf32 tensor cores (128x128 tiles)
    gemm_tf32_kernel<<<dim3(H_ / 128, (B_ * QL_) / 128), blk>>>(
        query, Wq, bq, nullptr, Qb, B_ * QL_, H_, H_, QL_, 1, nullptr);
    gemm_tf32_kernel<<<dim3(H_ / 128, (B_ * KL_) / 128), blk>>>(
        know, Wk, bk, nullptr, Kb, B_ * KL_, H_, H_, KL_, 1, ansst);
    gemm_tf32_kernel<<<dim3(H_ / 128, (B_ * KL_) / 128), blk>>>(
        know, Wv, bv, nullptr, Vb, B_ * KL_, H_, H_, KL_, 1, ansst);

    // Flash attention (fp32)
    cudaFuncSetAttribute(attn_kernel, cudaFuncAttributeMaxDynamicSharedMemorySize,
                         ATT_SMEM_BYTES);
    attn_kernel<<<dim3(QL_ / 64, NH_, B_), blk, ATT_SMEM_BYTES>>>(
        Qb, Kb, Vb, amask, ansst, Cb);

    // Output projection + bias + residual — tf32
    gemm_tf32_kernel<<<dim3(H_ / 128, (B_ * QL_) / 128), blk>>>(
        Cb, Wo, bo, query, Pb, B_ * QL_, H_, H_, 0, 0, nullptr);

    // LayerNorm
    ln_kernel<<<B_ * QL_, blk>>>(Pb, lnw, lnb, out);
}

// round 13
// speedup vs baseline: 2.7386x; 2.0413x over previous
#include <cuda_runtime.h>
#include <math.h>
#include <stdint.h>

#define B_   2
#define QL_  2048
#define KL_  4096
#define H_   1024
#define NH_  16
#define HD_  64
#define SCALE_ 0.125f
#define NEGINF (-INFINITY)

// ------------------------------------------------------------------
// Scratch (device globals: no allocations allowed)
// ------------------------------------------------------------------
__device__ float g_Q[(size_t)B_ * NH_ * QL_ * HD_];   // [b][h][q][hd]
__device__ float g_K[(size_t)B_ * NH_ * KL_ * HD_];   // [b][h][kv][hd]
__device__ float g_V[(size_t)B_ * NH_ * KL_ * HD_];
__device__ float g_ctx[(size_t)B_ * QL_ * H_];        // [b][q][h]
__device__ float g_pre[(size_t)B_ * QL_ * H_];        // pre-LN

// ------------------------------------------------------------------
// tf32 helpers (validated by R10 GEMM pass)
// ------------------------------------------------------------------
__device__ __forceinline__ uint32_t f2tf(float f) {
    uint32_t r;
    asm("cvt.rna.tf32.f32 %0, %1;" : "=r"(r) : "f"(f));
    return r;
}

__device__ __forceinline__ void mma_tf32(float* d, const uint32_t* a, const uint32_t* b) {
    asm volatile(
        "mma.sync.aligned.m16n8k8.row.col.f32.tf32.tf32.f32 "
        "{%0,%1,%2,%3}, {%4,%5,%6,%7}, {%8,%9}, {%0,%1,%2,%3};"
        : "+f"(d[0]), "+f"(d[1]), "+f"(d[2]), "+f"(d[3])
        : "r"(a[0]), "r"(a[1]), "r"(a[2]), "r"(a[3]), "r"(b[0]), "r"(b[1]));
}

// ------------------------------------------------------------------
// tf32 tensor-core GEMM (unchanged from passing R10):
// C[M,N] = A[M,K] @ W[K,N] + bias (+ residual); 128x128 CTA tile.
// ------------------------------------------------------------------
__global__ __launch_bounds__(256) void gemm_tf32_kernel(
    const float* __restrict__ A, const float* __restrict__ W,
    const float* __restrict__ bias, const float* __restrict__ residual,
    float* __restrict__ out, int M, int N, int K, int seq, int mode,
    const int* __restrict__ skip_ptr)
{
    __shared__ float As[32][136];   // [k][m]
    __shared__ float Ws[32][136];   // [k][n]

    const int m0 = blockIdx.y * 128;
    const int n0 = blockIdx.x * 128;

    if (mode == 1 && skip_ptr != nullptr) {
        int ansst = *skip_ptr;
        int s = m0 % seq;
        if (s + 128 <= ansst) return;
    }

    const int tid  = threadIdx.x;
    const int wid  = tid >> 5, lane = tid & 31;
    const int wm   = (wid >> 1) * 32;
    const int wn   = (wid & 1) * 64;
    const int g    = lane >> 2, t = lane & 3;

    float d[2][8][4];
    #pragma unroll
    for (int mm = 0; mm < 2; mm++)
        #pragma unroll
        for (int nn = 0; nn < 8; nn++)
            #pragma unroll
            for (int i = 0; i < 4; i++) d[mm][nn][i] = 0.0f;

    for (int k0 = 0; k0 < K; k0 += 32) {
        #pragma unroll
        for (int i = 0; i < 4; i++) {
            int idx  = tid + i * 256;
            int arow = idx >> 3, ac = (idx & 7) * 4;
            float4 av = *(const float4*)(A + (size_t)(m0 + arow) * K + k0 + ac);
            As[ac + 0][arow] = av.x;
            As[ac + 1][arow] = av.y;
            As[ac + 2][arow] = av.z;
            As[ac + 3][arow] = av.w;
            int wrow = idx >> 5, wc = (idx & 31) * 4;
            *(float4*)&Ws[wrow][wc] =
                *(const float4*)(W + (size_t)(k0 + wrow) * N + n0 + wc);
        }
        __syncthreads();

        #pragma unroll
        for (int kc = 0; kc < 32; kc += 8) {
            uint32_t a[2][4], b[8][2];
            #pragma unroll
            for (int mm = 0; mm < 2; mm++) {
                int mr = wm + mm * 16 + g;
                a[mm][0] = f2tf(As[kc + t    ][mr]);
                a[mm][1] = f2tf(As[kc + t    ][mr + 8]);
                a[mm][2] = f2tf(As[kc + t + 4][mr]);
                a[mm][3] = f2tf(As[kc + t + 4][mr + 8]);
            }
            #pragma unroll
            for (int nn = 0; nn < 8; nn++) {
                int nc = wn + nn * 8 + g;
                b[nn][0] = f2tf(Ws[kc + t    ][nc]);
                b[nn][1] = f2tf(Ws[kc + t + 4][nc]);
            }
            #pragma unroll
            for (int mm = 0; mm < 2; mm++)
                #pragma unroll
                for (int nn = 0; nn < 8; nn++)
                    mma_tf32(d[mm][nn], a[mm], b[nn]);
        }
        __syncthreads();
    }

    #pragma unroll
    for (int mm = 0; mm < 2; mm++) {
        #pragma unroll
        for (int nn = 0; nn < 8; nn++) {
            int r0 = m0 + wm + mm * 16 + g;
            int r1 = r0 + 8;
            int c0 = n0 + wn + nn * 8 + t * 2;
            float v00 = d[mm][nn][0] + bias[c0];
            float v01 = d[mm][nn][1] + bias[c0 + 1];
            float v10 = d[mm][nn][2] + bias[c0];
            float v11 = d[mm][nn][3] + bias[c0 + 1];
            if (mode == 0) {
                if (residual != nullptr) {
                    v00 += residual[(size_t)r0 * N + c0];
                    v01 += residual[(size_t)r0 * N + c0 + 1];
                    v10 += residual[(size_t)r1 * N + c0];
                    v11 += residual[(size_t)r1 * N + c0 + 1];
                }
                out[(size_t)r0 * N + c0]     = v00;
                out[(size_t)r0 * N + c0 + 1] = v01;
                out[(size_t)r1 * N + c0]     = v10;
                out[(size_t)r1 * N + c0 + 1] = v11;
            } else {
                int nh = c0 >> 6, hd = c0 & 63;
                int bb0 = r0 / seq, ss0 = r0 % seq;
                int bb1 = r1 / seq, ss1 = r1 % seq;
                size_t o0 = ((size_t)(bb0 * NH_ + nh) * seq + ss0) * HD_ + hd;
                size_t o1 = ((size_t)(bb1 * NH_ + nh) * seq + ss1) * HD_ + hd;
                out[o0]     = v00;
                out[o0 + 1] = v01;
                out[o1]     = v10;
                out[o1 + 1] = v11;
            }
        }
    }
}

// ------------------------------------------------------------------
// tf32 tensor-core flash attention.
// CTA: 128 q-rows x (head, batch); 8 warps, warp owns 16 q-rows.
// kv-tile 64. SMEM holds tf32 bit patterns (converted once at store).
// Strides: 68 (~4 mod 32) for row-varies-g fragment reads,
//          72 (~8 mod 32) for Vs (row varies t). All conflict-free.
// ------------------------------------------------------------------
#define ATQ_STRIDE 68
#define ATV_STRIDE 72
#define ATT2_SMEM_WORDS (128*68 + 64*68 + 64*72 + 128*68)   // 26368
#define ATT2_SMEM_BYTES (ATT2_SMEM_WORDS * 4)               // 105472

__global__ __launch_bounds__(256) void attn_tf32_kernel(
    const float* __restrict__ Qg_, const float* __restrict__ Kg_,
    const float* __restrict__ Vg_, const int* __restrict__ amask,
    const int* __restrict__ ansst_ptr, float* __restrict__ ctx)
{
    extern __shared__ uint32_t smu[];
    uint32_t* Qs = smu;                        // [128][68] tf32 (Q*scale)
    uint32_t* Ks = Qs + 128 * ATQ_STRIDE;      // [64][68]
    uint32_t* Vs = Ks + 64 * ATQ_STRIDE;       // [64][72]
    uint32_t* Ps = Vs + 64 * ATV_STRIDE;       // [128][68]

    const int qt = blockIdx.x, h = blockIdx.y, b = blockIdx.z;
    const int tid = threadIdx.x, wid = tid >> 5, lane = tid & 31;
    const int g = lane >> 2, t = lane & 3;
    const int wq0 = wid * 16;
    const int ansst = *ansst_ptr;

    const float* Qg = Qg_ + ((size_t)(b * NH_ + h) * QL_ + qt * 128) * HD_;
    const float* Kg = Kg_ + (size_t)(b * NH_ + h) * KL_ * HD_;
    const float* Vg = Vg_ + (size_t)(b * NH_ + h) * KL_ * HD_;

    // Load Q (128x64), fold softmax scale (exact: 2^-3), cvt to tf32.
    #pragma unroll
    for (int rep = 0; rep < 8; rep++) {
        int idx = tid + rep * 256;          // 2048 float4 total
        int row = idx >> 4, c4 = (idx & 15) * 4;
        float4 v = *(const float4*)(Qg + (size_t)row * HD_ + c4);
        uint32_t* qp = Qs + row * ATQ_STRIDE + c4;
        qp[0] = f2tf(v.x * SCALE_);
        qp[1] = f2tf(v.y * SCALE_);
        qp[2] = f2tf(v.z * SCALE_);
        qp[3] = f2tf(v.w * SCALE_);
    }

    const int qm0 = amask[b * QL_ + qt * 128 + wq0 + g];
    const int qm1 = amask[b * QL_ + qt * 128 + wq0 + g + 8];

    float m0 = NEGINF, m1 = NEGINF, l0 = 0.0f, l1 = 0.0f;
    float o[8][4];
    #pragma unroll
    for (int nn = 0; nn < 8; nn++)
        #pragma unroll
        for (int i = 0; i < 4; i++) o[nn][i] = 0.0f;

    const int t0 = (ansst > 0 ? ansst : 0) >> 6;
    for (int tt = t0; tt < KL_ / 64; tt++) {
        const int kv0 = tt * 64;
        // Load K,V tile (64x64 each), cvt to tf32 at store.
        #pragma unroll
        for (int rep = 0; rep < 4; rep++) {
            int idx = tid + rep * 256;       // 1024 float4 per matrix
            int row = idx >> 4, c4 = (idx & 15) * 4;
            float4 kv = *(const float4*)(Kg + (size_t)(kv0 + row) * HD_ + c4);
            uint32_t* kp = Ks + row * ATQ_STRIDE + c4;
            kp[0] = f2tf(kv.x); kp[1] = f2tf(kv.y);
            kp[2] = f2tf(kv.z); kp[3] = f2tf(kv.w);
            float4 vv = *(const float4*)(Vg + (size_t)(kv0 + row) * HD_ + c4);
            uint32_t* vp = Vs + row * ATV_STRIDE + c4;
            vp[0] = f2tf(vv.x); vp[1] = f2tf(vv.y);
            vp[2] = f2tf(vv.z); vp[3] = f2tf(vv.w);
        }
        __syncthreads();   // also covers initial Q store on first iter

        // ---- S = (Q*scale) @ K^T : warp computes 16 x 64 ----
        float s[8][4];
        #pragma unroll
        for (int nn = 0; nn < 8; nn++)
            #pragma unroll
            for (int i = 0; i < 4; i++) s[nn][i] = 0.0f;

        #pragma unroll
        for (int kc = 0; kc < 64; kc += 8) {
            uint32_t a[4];
            a[0] = Qs[(wq0 + g)     * ATQ_STRIDE + kc + t];
            a[1] = Qs[(wq0 + g + 8) * ATQ_STRIDE + kc + t];
            a[2] = Qs[(wq0 + g)     * ATQ_STRIDE + kc + t + 4];
            a[3] = Qs[(wq0 + g + 8) * ATQ_STRIDE + kc + t + 4];
            #pragma unroll
            for (int nn = 0; nn < 8; nn++) {
                uint32_t bf[2];
                bf[0] = Ks[(nn * 8 + g) * ATQ_STRIDE + kc + t];
                bf[1] = Ks[(nn * 8 + g) * ATQ_STRIDE + kc + t + 4];
                mma_tf32(s[nn], a, bf);
            }
        }

        // ---- masks ----
        if (kv0 < ansst) {                 // partial leading tile
            #pragma unroll
            for (int nn = 0; nn < 8; nn++) {
                int c0 = kv0 + nn * 8 + 2 * t;
                if (c0 < ansst)     { s[nn][0] = NEGINF; s[nn][2] = NEGINF; }
                if (c0 + 1 < ansst) { s[nn][1] = NEGINF; s[nn][3] = NEGINF; }
            }
        }
        if (qm0 == 0) {
            #pragma unroll
            for (int nn = 0; nn < 8; nn++) { s[nn][0] = NEGINF; s[nn][1] = NEGINF; }
        }
        if (qm1 == 0) {
            #pragma unroll
            for (int nn = 0; nn < 8; nn++) { s[nn][2] = NEGINF; s[nn][3] = NEGINF; }
        }

        // ---- online softmax (rows g, g+8 live on 4-lane quad) ----
        float mt0 = NEGINF, mt1 = NEGINF;
        #pragma unroll
        for (int nn = 0; nn < 8; nn++) {
            mt0 = fmaxf(mt0, fmaxf(s[nn][0], s[nn][1]));
            mt1 = fmaxf(mt1, fmaxf(s[nn][2], s[nn][3]));
        }
        mt0 = fmaxf(mt0, __shfl_xor_sync(0xffffffffu, mt0, 1));
        mt0 = fmaxf(mt0, __shfl_xor_sync(0xffffffffu, mt0, 2));
        mt1 = fmaxf(mt1, __shfl_xor_sync(0xffffffffu, mt1, 1));
        mt1 = fmaxf(mt1, __shfl_xor_sync(0xffffffffu, mt1, 2));

        float mn0 = fmaxf(m0, mt0), mn1 = fmaxf(m1, mt1);
        float sc0 = __expf(m0 - mn0), sc1 = __expf(m1 - mn1);
        m0 = mn0; m1 = mn1;

        float lt0 = 0.0f, lt1 = 0.0f;
        #pragma unroll
        for (int nn = 0; nn < 8; nn++) {
            float p00 = __expf(s[nn][0] - mn0);
            float p01 = __expf(s[nn][1] - mn0);
            float p10 = __expf(s[nn][2] - mn1);
            float p11 = __expf(s[nn][3] - mn1);
            lt0 += p00 + p01;
            lt1 += p10 + p11;
            uint2 u0; u0.x = f2tf(p00); u0.y = f2tf(p01);
            uint2 u1; u1.x = f2tf(p10); u1.y = f2tf(p11);
            *(uint2*)&Ps[(wq0 + g)     * ATQ_STRIDE + nn * 8 + 2 * t] = u0;
            *(uint2*)&Ps[(wq0 + g + 8) * ATQ_STRIDE + nn * 8 + 2 * t] = u1;
        }
        lt0 += __shfl_xor_sync(0xffffffffu, lt0, 1);
        lt0 += __shfl_xor_sync(0xffffffffu, lt0, 2);
        lt1 += __shfl_xor_sync(0xffffffffu, lt1, 1);
        lt1 += __shfl_xor_sync(0xffffffffu, lt1, 2);
        l0 = l0 * sc0 + lt0;
        l1 = l1 * sc1 + lt1;
        #pragma unroll
        for (int nn = 0; nn < 8; nn++) {
            o[nn][0] *= sc0; o[nn][1] *= sc0;
            o[nn][2] *= sc1; o[nn][3] *= sc1;
        }

        // ---- O += P @ V (warp reads only its own Ps rows: no barrier) ----
        #pragma unroll
        for (int kc = 0; kc < 64; kc += 8) {
            uint32_t a[4];
            a[0] = Ps[(wq0 + g)     * ATQ_STRIDE + kc + t];
            a[1] = Ps[(wq0 + g + 8) * ATQ_STRIDE + kc + t];
            a[2] = Ps[(wq0 + g)     * ATQ_STRIDE + kc + t + 4];
            a[3] = Ps[(wq0 + g + 8) * ATQ_STRIDE + kc + t + 4];
            #pragma unroll
            for (int nn = 0; nn < 8; nn++) {
                uint32_t bf[2];
                bf[0] = Vs[(kc + t)     * ATV_STRIDE + nn * 8 + g];
                bf[1] = Vs[(kc + t + 4) * ATV_STRIDE + nn * 8 + g];
                mma_tf32(o[nn], a, bf);
            }
        }
        __syncthreads();   // before next tile overwrites Ks/Vs
    }

    // ---- epilogue: normalize, write ctx[b][q][h] ----
    float inv0 = 1.0f / l0, inv1 = 1.0f / l1;
    int q0 = qt * 128 + wq0 + g;
    int q1 = q0 + 8;
    #pragma unroll
    for (int nn = 0; nn < 8; nn++) {
        int col = h * HD_ + nn * 8 + 2 * t;
        float2 r0; r0.x = o[nn][0] * inv0; r0.y = o[nn][1] * inv0;
        float2 r1; r1.x = o[nn][2] * inv1; r1.y = o[nn][3] * inv1;
        *(float2*)(ctx + (size_t)(b * QL_ + q0) * H_ + col) = r0;
        *(float2*)(ctx + (size_t)(b * QL_ + q1) * H_ + col) = r1;
    }
}

// ------------------------------------------------------------------
// LayerNorm: one block (256 threads) per row of 1024
// ------------------------------------------------------------------
__global__ __launch_bounds__(256) void ln_kernel(
    const float* __restrict__ x, const float* __restrict__ w,
    const float* __restrict__ bb, float* __restrict__ out)
{
    const int row = blockIdx.x, tid = threadIdx.x;
    const float* xr = x + (size_t)row * H_;
    float4 v = *(const float4*)(xr + tid * 4);
    float s = v.x + v.y + v.z + v.w;
    #pragma unroll
    for (int off = 16; off > 0; off >>= 1) s += __shfl_xor_sync(0xffffffffu, s, off);
    __shared__ float b1[8], b2[8];
    int wid = tid >> 5, lane = tid & 31;
    if (lane == 0) b1[wid] = s;
    __syncthreads();
    float tot = 0.0f;
    #pragma unroll
    for (int i = 0; i < 8; i++) tot += b1[i];
    float mean = tot * (1.0f / H_);
    float dx = v.x - mean, dy = v.y - mean, dz = v.z - mean, dw = v.w - mean;
    float s2 = dx * dx + dy * dy + dz * dz + dw * dw;
    #pragma unroll
    for (int off = 16; off > 0; off >>= 1) s2 += __shfl_xor_sync(0xffffffffu, s2, off);
    if (lane == 0) b2[wid] = s2;
    __syncthreads();
    float tot2 = 0.0f;
    #pragma unroll
    for (int i = 0; i < 8; i++) tot2 += b2[i];
    float rstd = rsqrtf(tot2 * (1.0f / H_) + 1e-5f);
    float4 wv = *(const float4*)(w + tid * 4);
    float4 bv = *(const float4*)(bb + tid * 4);
    float4 r;
    r.x = dx * rstd * wv.x + bv.x;
    r.y = dy * rstd * wv.y + bv.y;
    r.z = dz * rstd * wv.z + bv.z;
    r.w = dw * rstd * wv.w + bv.w;
    *(float4*)(out + (size_t)row * H_ + tid * 4) = r;
}

// ------------------------------------------------------------------
extern "C" void kernel_launch(void* const* d_in, const int* in_sizes, int n_in,
                              void* d_out, int out_size)
{
    const float* query = (const float*)d_in[0];
    const float* know  = (const float*)d_in[1];
    const int*   amask = (const int*)d_in[2];
    const int*   ansst = (const int*)d_in[3];
    const float* Wq = (const float*)d_in[4];
    const float* bq = (const float*)d_in[5];
    const float* Wk = (const float*)d_in[6];
    const float* bk = (const float*)d_in[7];
    const float* Wv = (const float*)d_in[8];
    const float* bv = (const float*)d_in[9];
    const float* Wo = (const float*)d_in[10];
    const float* bo = (const float*)d_in[11];
    const float* lnw = (const float*)d_in[12];
    const float* lnb = (const float*)d_in[13];
    float* out = (float*)d_out;

    float *Qb, *Kb, *Vb, *Cb, *Pb;
    cudaGetSymbolAddress((void**)&Qb, g_Q);
    cudaGetSymbolAddress((void**)&Kb, g_K);
    cudaGetSymbolAddress((void**)&Vb, g_V);
    cudaGetSymbolAddress((void**)&Cb, g_ctx);
    cudaGetSymbolAddress((void**)&Pb, g_pre);

    const dim3 blk(256);

    // Q / K / V projections — tf32 tensor cores
    gemm_tf32_kernel<<<dim3(H_ / 128, (B_ * QL_) / 128), blk>>>(
        query, Wq, bq, nullptr, Qb, B_ * QL_, H_, H_, QL_, 1, nullptr);
    gemm_tf32_kernel<<<dim3(H_ / 128, (B_ * KL_) / 128), blk>>>(
        know, Wk, bk, nullptr, Kb, B_ * KL_, H_, H_, KL_, 1, ansst);
    gemm_tf32_kernel<<<dim3(H_ / 128, (B_ * KL_) / 128), blk>>>(
        know, Wv, bv, nullptr, Vb, B_ * KL_, H_, H_, KL_, 1, ansst);

    // Flash attention — tf32 tensor cores
    cudaFuncSetAttribute(attn_tf32_kernel,
                         cudaFuncAttributeMaxDynamicSharedMemorySize,
                         ATT2_SMEM_BYTES);
    attn_tf32_kernel<<<dim3(QL_ / 128, NH_, B_), blk, ATT2_SMEM_BYTES>>>(
        Qb, Kb, Vb, amask, ansst, Cb);

    // Output projection + bias + residual — tf32
    gemm_tf32_kernel<<<dim3(H_ / 128, (B_ * QL_) / 128), blk>>>(
        Cb, Wo, bo, query, Pb, B_ * QL_, H_, H_, 0, 0, nullptr);

    // LayerNorm
    ln_kernel<<<B_ * QL_, blk>>>(Pb, lnw, lnb, out);
}

// round 17
// speedup vs baseline: 2.8482x; 1.0400x over previous
#include <cuda_runtime.h>
#include <math.h>
#include <stdint.h>

#define B_   2
#define QL_  2048
#define KL_  4096
#define H_   1024
#define NH_  16
#define HD_  64
#define SCALE_ 0.125f
#define NEGINF (-INFINITY)

// ------------------------------------------------------------------
// Scratch (device globals: no allocations allowed)
// ------------------------------------------------------------------
__device__ float g_Q[(size_t)B_ * NH_ * QL_ * HD_];   // [b][h][q][hd]
__device__ float g_K[(size_t)B_ * NH_ * KL_ * HD_];   // [b][h][kv][hd]
__device__ float g_V[(size_t)B_ * NH_ * KL_ * HD_];
__device__ float g_ctx[(size_t)B_ * QL_ * H_];        // [b][q][h]
__device__ float g_pre[(size_t)B_ * QL_ * H_];        // pre-LN

// ------------------------------------------------------------------
// tf32 helpers (validated R10/R13)
// ------------------------------------------------------------------
__device__ __forceinline__ uint32_t f2tf(float f) {
    uint32_t r;
    asm("cvt.rna.tf32.f32 %0, %1;" : "=r"(r) : "f"(f));
    return r;
}

__device__ __forceinline__ void mma_tf32(float* d, const uint32_t* a, const uint32_t* b) {
    asm volatile(
        "mma.sync.aligned.m16n8k8.row.col.f32.tf32.tf32.f32 "
        "{%0,%1,%2,%3}, {%4,%5,%6,%7}, {%8,%9}, {%0,%1,%2,%3};"
        : "+f"(d[0]), "+f"(d[1]), "+f"(d[2]), "+f"(d[3])
        : "r"(a[0]), "r"(a[1]), "r"(a[2]), "r"(a[3]), "r"(b[0]), "r"(b[1]));
}

// ------------------------------------------------------------------
// tf32 tensor-core GEMM (unchanged from passing R10/R13):
// C[M,N] = A[M,K] @ W[K,N] + bias (+ residual); 128x128 CTA tile.
// ------------------------------------------------------------------
__global__ __launch_bounds__(256) void gemm_tf32_kernel(
    const float* __restrict__ A, const float* __restrict__ W,
    const float* __restrict__ bias, const float* __restrict__ residual,
    float* __restrict__ out, int M, int N, int K, int seq, int mode,
    const int* __restrict__ skip_ptr)
{
    __shared__ float As[32][136];   // [k][m]
    __shared__ float Ws[32][136];   // [k][n]

    const int m0 = blockIdx.y * 128;
    const int n0 = blockIdx.x * 128;

    if (mode == 1 && skip_ptr != nullptr) {
        int ansst = *skip_ptr;
        int s = m0 % seq;
        if (s + 128 <= ansst) return;
    }

    const int tid  = threadIdx.x;
    const int wid  = tid >> 5, lane = tid & 31;
    const int wm   = (wid >> 1) * 32;
    const int wn   = (wid & 1) * 64;
    const int g    = lane >> 2, t = lane & 3;

    float d[2][8][4];
    #pragma unroll
    for (int mm = 0; mm < 2; mm++)
        #pragma unroll
        for (int nn = 0; nn < 8; nn++)
            #pragma unroll
            for (int i = 0; i < 4; i++) d[mm][nn][i] = 0.0f;

    for (int k0 = 0; k0 < K; k0 += 32) {
        #pragma unroll
        for (int i = 0; i < 4; i++) {
            int idx  = tid + i * 256;
            int arow = idx >> 3, ac = (idx & 7) * 4;
            float4 av = *(const float4*)(A + (size_t)(m0 + arow) * K + k0 + ac);
            As[ac + 0][arow] = av.x;
            As[ac + 1][arow] = av.y;
            As[ac + 2][arow] = av.z;
            As[ac + 3][arow] = av.w;
            int wrow = idx >> 5, wc = (idx & 31) * 4;
            *(float4*)&Ws[wrow][wc] =
                *(const float4*)(W + (size_t)(k0 + wrow) * N + n0 + wc);
        }
        __syncthreads();

        #pragma unroll
        for (int kc = 0; kc < 32; kc += 8) {
            uint32_t a[2][4], b[8][2];
            #pragma unroll
            for (int mm = 0; mm < 2; mm++) {
                int mr = wm + mm * 16 + g;
                a[mm][0] = f2tf(As[kc + t    ][mr]);
                a[mm][1] = f2tf(As[kc + t    ][mr + 8]);
                a[mm][2] = f2tf(As[kc + t + 4][mr]);
                a[mm][3] = f2tf(As[kc + t + 4][mr + 8]);
            }
            #pragma unroll
            for (int nn = 0; nn < 8; nn++) {
                int nc = wn + nn * 8 + g;
                b[nn][0] = f2tf(Ws[kc + t    ][nc]);
                b[nn][1] = f2tf(Ws[kc + t + 4][nc]);
            }
            #pragma unroll
            for (int mm = 0; mm < 2; mm++)
                #pragma unroll
                for (int nn = 0; nn < 8; nn++)
                    mma_tf32(d[mm][nn], a[mm], b[nn]);
        }
        __syncthreads();
    }

    #pragma unroll
    for (int mm = 0; mm < 2; mm++) {
        #pragma unroll
        for (int nn = 0; nn < 8; nn++) {
            int r0 = m0 + wm + mm * 16 + g;
            int r1 = r0 + 8;
            int c0 = n0 + wn + nn * 8 + t * 2;
            float v00 = d[mm][nn][0] + bias[c0];
            float v01 = d[mm][nn][1] + bias[c0 + 1];
            float v10 = d[mm][nn][2] + bias[c0];
            float v11 = d[mm][nn][3] + bias[c0 + 1];
            if (mode == 0) {
                if (residual != nullptr) {
                    v00 += residual[(size_t)r0 * N + c0];
                    v01 += residual[(size_t)r0 * N + c0 + 1];
                    v10 += residual[(size_t)r1 * N + c0];
                    v11 += residual[(size_t)r1 * N + c0 + 1];
                }
                out[(size_t)r0 * N + c0]     = v00;
                out[(size_t)r0 * N + c0 + 1] = v01;
                out[(size_t)r1 * N + c0]     = v10;
                out[(size_t)r1 * N + c0 + 1] = v11;
            } else {
                int nh = c0 >> 6, hd = c0 & 63;
                int bb0 = r0 / seq, ss0 = r0 % seq;
                int bb1 = r1 / seq, ss1 = r1 % seq;
                size_t o0 = ((size_t)(bb0 * NH_ + nh) * seq + ss0) * HD_ + hd;
                size_t o1 = ((size_t)(bb1 * NH_ + nh) * seq + ss1) * HD_ + hd;
                out[o0]     = v00;
                out[o0 + 1] = v01;
                out[o1]     = v10;
                out[o1 + 1] = v11;
            }
        }
    }
}

// ------------------------------------------------------------------
// tf32 flash attention v2: 128 q-rows/CTA, 4 warps x 32 rows (mm=2),
// register-resident P via permuted K rows (c-frag == PV a-frag),
// kv-tile 64. SMEM: Qs[128][68] Ks[64][68] Vs[64][72] = 70656 B -> 3 CTA/SM.
// perm(g) = (g&1)*4 + (g>>1): c-frag slot (g, 2t+e) holds kv = nn*8+t+4e.
// ------------------------------------------------------------------
#define ATQ_STRIDE 68
#define ATV_STRIDE 72
#define ATT3_SMEM_WORDS (128*ATQ_STRIDE + 64*ATQ_STRIDE + 64*ATV_STRIDE)
#define ATT3_SMEM_BYTES (ATT3_SMEM_WORDS * 4)   // 70656

__global__ __launch_bounds__(128, 3) void attn_tf32_kernel(
    const float* __restrict__ Qg_, const float* __restrict__ Kg_,
    const float* __restrict__ Vg_, const int* __restrict__ amask,
    const int* __restrict__ ansst_ptr, float* __restrict__ ctx)
{
    extern __shared__ uint32_t smu[];
    uint32_t* Qs = smu;                        // [128][68] tf32 (Q*scale)
    uint32_t* Ks = Qs + 128 * ATQ_STRIDE;      // [64][68]
    uint32_t* Vs = Ks + 64 * ATQ_STRIDE;       // [64][72]

    const int qt = blockIdx.x, h = blockIdx.y, b = blockIdx.z;
    const int tid = threadIdx.x, wid = tid >> 5, lane = tid & 31;
    const int g = lane >> 2, t = lane & 3;
    const int permg = (g & 1) * 4 + (g >> 1);  // K-row permutation
    const int wq0 = wid * 32;
    const int ansst = *ansst_ptr;

    const float* Qg = Qg_ + ((size_t)(b * NH_ + h) * QL_ + qt * 128) * HD_;
    const float* Kg = Kg_ + (size_t)(b * NH_ + h) * KL_ * HD_;
    const float* Vg = Vg_ + (size_t)(b * NH_ + h) * KL_ * HD_;

    // Load Q (128x64), fold scale (exact 2^-3), cvt tf32. 2048 float4, 16 reps.
    #pragma unroll
    for (int rep = 0; rep < 16; rep++) {
        int idx = tid + rep * 128;
        int row = idx >> 4, c4 = (idx & 15) * 4;
        float4 v = *(const float4*)(Qg + (size_t)row * HD_ + c4);
        uint32_t* qp = Qs + row * ATQ_STRIDE + c4;
        qp[0] = f2tf(v.x * SCALE_);
        qp[1] = f2tf(v.y * SCALE_);
        qp[2] = f2tf(v.z * SCALE_);
        qp[3] = f2tf(v.w * SCALE_);
    }

    int qm[2][2];
    #pragma unroll
    for (int mm = 0; mm < 2; mm++) {
        qm[mm][0] = amask[b * QL_ + qt * 128 + wq0 + mm * 16 + g];
        qm[mm][1] = amask[b * QL_ + qt * 128 + wq0 + mm * 16 + g + 8];
    }

    float m_[2][2], l_[2][2];
    float o[2][8][4];
    #pragma unroll
    for (int mm = 0; mm < 2; mm++) {
        m_[mm][0] = NEGINF; m_[mm][1] = NEGINF;
        l_[mm][0] = 0.0f;   l_[mm][1] = 0.0f;
        #pragma unroll
        for (int nn = 0; nn < 8; nn++)
            #pragma unroll
            for (int i = 0; i < 4; i++) o[mm][nn][i] = 0.0f;
    }

    const int t0 = (ansst > 0 ? ansst : 0) >> 6;
    for (int tt = t0; tt < KL_ / 64; tt++) {
        const int kv0 = tt * 64;
        // Load K,V tile (64x64 each), cvt tf32. 1024 float4 each, 8 reps.
        #pragma unroll
        for (int rep = 0; rep < 8; rep++) {
            int idx = tid + rep * 128;
            int row = idx >> 4, c4 = (idx & 15) * 4;
            float4 kv = *(const float4*)(Kg + (size_t)(kv0 + row) * HD_ + c4);
            uint32_t* kp = Ks + row * ATQ_STRIDE + c4;
            kp[0] = f2tf(kv.x); kp[1] = f2tf(kv.y);
            kp[2] = f2tf(kv.z); kp[3] = f2tf(kv.w);
            float4 vv = *(const float4*)(Vg + (size_t)(kv0 + row) * HD_ + c4);
            uint32_t* vp = Vs + row * ATV_STRIDE + c4;
            vp[0] = f2tf(vv.x); vp[1] = f2tf(vv.y);
            vp[2] = f2tf(vv.z); vp[3] = f2tf(vv.w);
        }
        __syncthreads();   // also covers initial Q store on first iter

        // ---- S = (Q*scale) @ K^T, K rows permuted (perm(g)) ----
        float s[2][8][4];
        #pragma unroll
        for (int mm = 0; mm < 2; mm++)
            #pragma unroll
            for (int nn = 0; nn < 8; nn++)
                #pragma unroll
                for (int i = 0; i < 4; i++) s[mm][nn][i] = 0.0f;

        #pragma unroll
        for (int kc = 0; kc < 64; kc += 8) {
            uint32_t a[2][4];
            #pragma unroll
            for (int mm = 0; mm < 2; mm++) {
                int mr = wq0 + mm * 16 + g;
                a[mm][0] = Qs[mr * ATQ_STRIDE + kc + t];
                a[mm][1] = Qs[(mr + 8) * ATQ_STRIDE + kc + t];
                a[mm][2] = Qs[mr * ATQ_STRIDE + kc + t + 4];
                a[mm][3] = Qs[(mr + 8) * ATQ_STRIDE + kc + t + 4];
            }
            #pragma unroll
            for (int nn = 0; nn < 8; nn++) {
                uint32_t bf[2];
                bf[0] = Ks[(nn * 8 + permg) * ATQ_STRIDE + kc + t];
                bf[1] = Ks[(nn * 8 + permg) * ATQ_STRIDE + kc + t + 4];
                #pragma unroll
                for (int mm = 0; mm < 2; mm++)
                    mma_tf32(s[mm][nn], a[mm], bf);
            }
        }

        // ---- masks (permuted slot->kv: slot0/2 -> nn*8+t, slot1/3 -> nn*8+t+4) ----
        if (kv0 < ansst) {
            #pragma unroll
            for (int nn = 0; nn < 8; nn++) {
                int kva = kv0 + nn * 8 + t;
                int kvb = kva + 4;
                #pragma unroll
                for (int mm = 0; mm < 2; mm++) {
                    if (kva < ansst) { s[mm][nn][0] = NEGINF; s[mm][nn][2] = NEGINF; }
                    if (kvb < ansst) { s[mm][nn][1] = NEGINF; s[mm][nn][3] = NEGINF; }
                }
            }
        }
        #pragma unroll
        for (int mm = 0; mm < 2; mm++) {
            if (qm[mm][0] == 0)
                #pragma unroll
                for (int nn = 0; nn < 8; nn++) { s[mm][nn][0] = NEGINF; s[mm][nn][1] = NEGINF; }
            if (qm[mm][1] == 0)
                #pragma unroll
                for (int nn = 0; nn < 8; nn++) { s[mm][nn][2] = NEGINF; s[mm][nn][3] = NEGINF; }
        }

        // ---- online softmax (rows live on 4-lane quads); p -> tf32 in place ----
        #pragma unroll
        for (int mm = 0; mm < 2; mm++) {
            float mt0 = NEGINF, mt1 = NEGINF;
            #pragma unroll
            for (int nn = 0; nn < 8; nn++) {
                mt0 = fmaxf(mt0, fmaxf(s[mm][nn][0], s[mm][nn][1]));
                mt1 = fmaxf(mt1, fmaxf(s[mm][nn][2], s[mm][nn][3]));
            }
            mt0 = fmaxf(mt0, __shfl_xor_sync(0xffffffffu, mt0, 1));
            mt0 = fmaxf(mt0, __shfl_xor_sync(0xffffffffu, mt0, 2));
            mt1 = fmaxf(mt1, __shfl_xor_sync(0xffffffffu, mt1, 1));
            mt1 = fmaxf(mt1, __shfl_xor_sync(0xffffffffu, mt1, 2));

            float mn0 = fmaxf(m_[mm][0], mt0), mn1 = fmaxf(m_[mm][1], mt1);
            float sc0 = __expf(m_[mm][0] - mn0), sc1 = __expf(m_[mm][1] - mn1);
            m_[mm][0] = mn0; m_[mm][1] = mn1;

            float lt0 = 0.0f, lt1 = 0.0f;
            #pragma unroll
            for (int nn = 0; nn < 8; nn++) {
                float p0 = __expf(s[mm][nn][0] - mn0);
                float p1 = __expf(s[mm][nn][1] - mn0);
                float p2 = __expf(s[mm][nn][2] - mn1);
                float p3 = __expf(s[mm][nn][3] - mn1);
                lt0 += p0 + p1;
                lt1 += p2 + p3;
                s[mm][nn][0] = __uint_as_float(f2tf(p0));
                s[mm][nn][1] = __uint_as_float(f2tf(p1));
                s[mm][nn][2] = __uint_as_float(f2tf(p2));
                s[mm][nn][3] = __uint_as_float(f2tf(p3));
            }
            lt0 += __shfl_xor_sync(0xffffffffu, lt0, 1);
            lt0 += __shfl_xor_sync(0xffffffffu, lt0, 2);
            lt1 += __shfl_xor_sync(0xffffffffu, lt1, 1);
            lt1 += __shfl_xor_sync(0xffffffffu, lt1, 2);
            l_[mm][0] = l_[mm][0] * sc0 + lt0;
            l_[mm][1] = l_[mm][1] * sc1 + lt1;
            #pragma unroll
            for (int nn = 0; nn < 8; nn++) {
                o[mm][nn][0] *= sc0; o[mm][nn][1] *= sc0;
                o[mm][nn][2] *= sc1; o[mm][nn][3] *= sc1;
            }
        }

        // ---- O += P @ V : P c-frag IS the a-frag (a0=s0, a1=s2, a2=s1, a3=s3) ----
        #pragma unroll
        for (int nn = 0; nn < 8; nn++) {          // kv chunk kc = nn*8
            uint32_t a[2][4];
            #pragma unroll
            for (int mm = 0; mm < 2; mm++) {
                a[mm][0] = __float_as_uint(s[mm][nn][0]);
                a[mm][1] = __float_as_uint(s[mm][nn][2]);
                a[mm][2] = __float_as_uint(s[mm][nn][1]);
                a[mm][3] = __float_as_uint(s[mm][nn][3]);
            }
            #pragma unroll
            for (int nn2 = 0; nn2 < 8; nn2++) {   // hd chunk
                uint32_t bf[2];
                bf[0] = Vs[(nn * 8 + t)     * ATV_STRIDE + nn2 * 8 + g];
                bf[1] = Vs[(nn * 8 + t + 4) * ATV_STRIDE + nn2 * 8 + g];
                #pragma unroll
                for (int mm = 0; mm < 2; mm++)
                    mma_tf32(o[mm][nn2], a[mm], bf);
            }
        }
        __syncthreads();   // before next tile overwrites Ks/Vs
    }

    // ---- epilogue: normalize, write ctx[b][q][h] ----
    #pragma unroll
    for (int mm = 0; mm < 2; mm++) {
        float inv0 = 1.0f / l_[mm][0], inv1 = 1.0f / l_[mm][1];
        int q0 = qt * 128 + wq0 + mm * 16 + g;
        int q1 = q0 + 8;
        #pragma unroll
        for (int nn = 0; nn < 8; nn++) {
            int col = h * HD_ + nn * 8 + 2 * t;
            float2 r0; r0.x = o[mm][nn][0] * inv0; r0.y = o[mm][nn][1] * inv0;
            float2 r1; r1.x = o[mm][nn][2] * inv1; r1.y = o[mm][nn][3] * inv1;
            *(float2*)(ctx + (size_t)(b * QL_ + q0) * H_ + col) = r0;
            *(float2*)(ctx + (size_t)(b * QL_ + q1) * H_ + col) = r1;
        }
    }
}

// ------------------------------------------------------------------
// LayerNorm: one block (256 threads) per row of 1024
// ------------------------------------------------------------------
__global__ __launch_bounds__(256) void ln_kernel(
    const float* __restrict__ x, const float* __restrict__ w,
    const float* __restrict__ bb, float* __restrict__ out)
{
    const int row = blockIdx.x, tid = threadIdx.x;
    const float* xr = x + (size_t)row * H_;
    float4 v = *(const float4*)(xr + tid * 4);
    float s = v.x + v.y + v.z + v.w;
    #pragma unroll
    for (int off = 16; off > 0; off >>= 1) s += __shfl_xor_sync(0xffffffffu, s, off);
    __shared__ float b1[8], b2[8];
    int wid = tid >> 5, lane = tid & 31;
    if (lane == 0) b1[wid] = s;
    __syncthreads();
    float tot = 0.0f;
    #pragma unroll
    for (int i = 0; i < 8; i++) tot += b1[i];
    float mean = tot * (1.0f / H_);
    float dx = v.x - mean, dy = v.y - mean, dz = v.z - mean, dw = v.w - mean;
    float s2 = dx * dx + dy * dy + dz * dz + dw * dw;
    #pragma unroll
    for (int off = 16; off > 0; off >>= 1) s2 += __shfl_xor_sync(0xffffffffu, s2, off);
    if (lane == 0) b2[wid] = s2;
    __syncthreads();
    float tot2 = 0.0f;
    #pragma unroll
    for (int i = 0; i < 8; i++) tot2 += b2[i];
    float rstd = rsqrtf(tot2 * (1.0f / H_) + 1e-5f);
    float4 wv = *(const float4*)(w + tid * 4);
    float4 bv = *(const float4*)(bb + tid * 4);
    float4 r;
    r.x = dx * rstd * wv.x + bv.x;
    r.y = dy * rstd * wv.y + bv.y;
    r.z = dz * rstd * wv.z + bv.z;
    r.w = dw * rstd * wv.w + bv.w;
    *(float4*)(out + (size_t)row * H_ + tid * 4) = r;
}

// ------------------------------------------------------------------
extern "C" void kernel_launch(void* const* d_in, const int* in_sizes, int n_in,
                              void* d_out, int out_size)
{
    const float* query = (const float*)d_in[0];
    const float* know  = (const float*)d_in[1];
    const int*   amask = (const int*)d_in[2];
    const int*   ansst = (const int*)d_in[3];
    const float* Wq = (const float*)d_in[4];
    const float* bq = (const float*)d_in[5];
    const float* Wk = (const float*)d_in[6];
    const float* bk = (const float*)d_in[7];
    const float* Wv = (const float*)d_in[8];
    const float* bv = (const float*)d_in[9];
    const float* Wo = (const float*)d_in[10];
    const float* bo = (const float*)d_in[11];
    const float* lnw = (const float*)d_in[12];
    const float* lnb = (const float*)d_in[13];
    float* out = (float*)d_out;

    float *Qb, *Kb, *Vb, *Cb, *Pb;
    cudaGetSymbolAddress((void**)&Qb, g_Q);
    cudaGetSymbolAddress((void**)&Kb, g_K);
    cudaGetSymbolAddress((void**)&Vb, g_V);
    cudaGetSymbolAddress((void**)&Cb, g_ctx);
    cudaGetSymbolAddress((void**)&Pb, g_pre);

    const dim3 blk(256);

    // Q / K / V projections — tf32 tensor cores
    gemm_tf32_kernel<<<dim3(H_ / 128, (B_ * QL_) / 128), blk>>>(
        query, Wq, bq, nullptr, Qb, B_ * QL_, H_, H_, QL_, 1, nullptr);
    gemm_tf32_kernel<<<dim3(H_ / 128, (B_ * KL_) / 128), blk>>>(
        know, Wk, bk, nullptr, Kb, B_ * KL_, H_, H_, KL_, 1, ansst);
    gemm_tf32_kernel<<<dim3(H_ / 128, (B_ * KL_) / 128), blk>>>(
        know, Wv, bv, nullptr, Vb, B_ * KL_, H_, H_, KL_, 1, ansst);

    // Flash attention — tf32, register-resident P, 128 threads/CTA
    cudaFuncSetAttribute(attn_tf32_kernel,
                         cudaFuncAttributeMaxDynamicSharedMemorySize,
                         ATT3_SMEM_BYTES);
    attn_tf32_kernel<<<dim3(QL_ / 128, NH_, B_), dim3(128), ATT3_SMEM_BYTES>>>(
        Qb, Kb, Vb, amask, ansst, Cb);

    // Output projection + bias + residual — tf32
    gemm_tf32_kernel<<<dim3(H_ / 128, (B_ * QL_) / 128), blk>>>(
        Cb, Wo, bo, query, Pb, B_ * QL_, H_, H_, 0, 0, nullptr);

    // LayerNorm
    ln_kernel<<<B_ * QL_, blk>>>(Pb, lnw, lnb, out);
}